// round 4
// baseline (speedup 1.0000x reference)
#include <cuda_runtime.h>
#include <math.h>

#define NNODES 50000
#define NEDGES 800000
#define FDIM   128
#define TM     64

// ---- scratch (static device memory; no allocations allowed) ----
__device__ float g_W[FDIM * FDIM];          // evolved weight, row-major [k][j]
__device__ float g_xw[NNODES * FDIM];       // x @ W
__device__ float g_deg[NNODES];
__device__ float g_dinv[NNODES];
__device__ int   g_counts[NNODES];
__device__ int   g_offsets[NNODES + 1];
__device__ int   g_cursor[NNODES];
__device__ int   g_csr_src[NEDGES];
__device__ float g_csr_norm[NEDGES];

// ---------------------------------------------------------------------------
// K1: GRU evolve.  W = (1-z)*n + z*W0 with gates from W0@W_ih^T, W0@W_hh^T.
// block i = row of W0, thread j = output column (of the F-sized gate slice).
// ---------------------------------------------------------------------------
__global__ void k_evolve(const float* __restrict__ W0,
                         const float* __restrict__ Wih,
                         const float* __restrict__ Whh,
                         const float* __restrict__ bih,
                         const float* __restrict__ bhh) {
    int i = blockIdx.x;
    int j = threadIdx.x;
    __shared__ float w0row[FDIM];
    w0row[j] = W0[i * FDIM + j];
    __syncthreads();

    const float4* w0r4 = (const float4*)w0row;
    const float4* Wih4 = (const float4*)Wih;
    const float4* Whh4 = (const float4*)Whh;

    float gir = 0.f, giz = 0.f, gin = 0.f;
    float ghr = 0.f, ghz = 0.f, ghn = 0.f;
#pragma unroll
    for (int k4 = 0; k4 < FDIM / 4; k4++) {
        float4 a = w0r4[k4];
        float4 v;
        v = Wih4[(j)             * 32 + k4]; gir += a.x*v.x + a.y*v.y + a.z*v.z + a.w*v.w;
        v = Wih4[(FDIM + j)      * 32 + k4]; giz += a.x*v.x + a.y*v.y + a.z*v.z + a.w*v.w;
        v = Wih4[(2 * FDIM + j)  * 32 + k4]; gin += a.x*v.x + a.y*v.y + a.z*v.z + a.w*v.w;
        v = Whh4[(j)             * 32 + k4]; ghr += a.x*v.x + a.y*v.y + a.z*v.z + a.w*v.w;
        v = Whh4[(FDIM + j)      * 32 + k4]; ghz += a.x*v.x + a.y*v.y + a.z*v.z + a.w*v.w;
        v = Whh4[(2 * FDIM + j)  * 32 + k4]; ghn += a.x*v.x + a.y*v.y + a.z*v.z + a.w*v.w;
    }
    gir += bih[j]; giz += bih[FDIM + j]; gin += bih[2 * FDIM + j];
    ghr += bhh[j]; ghz += bhh[FDIM + j]; ghn += bhh[2 * FDIM + j];

    float r = 1.f / (1.f + expf(-(gir + ghr)));
    float z = 1.f / (1.f + expf(-(giz + ghz)));
    float n = tanhf(gin + r * ghn);
    g_W[i * FDIM + j] = (1.f - z) * n + z * w0row[j];
}

// ---------------------------------------------------------------------------
// K2: init deg (self-loop weight 1 pre-added) and counts.
// ---------------------------------------------------------------------------
__global__ void k_init(int n) {
    int i = blockIdx.x * blockDim.x + threadIdx.x;
    if (i < n) { g_deg[i] = 1.0f; g_counts[i] = 0; }
}

// K3: degree + in-degree counts over real edges.
__global__ void k_edge_count(const int* __restrict__ dst,
                             const float* __restrict__ w, int E) {
    int e = blockIdx.x * blockDim.x + threadIdx.x;
    if (e < E) {
        int d = dst[e];
        atomicAdd(&g_deg[d], w[e]);
        atomicAdd(&g_counts[d], 1);
    }
}

// K4: dinv = rsqrt(deg)  (deg >= 1 always, because of self-loop)
__global__ void k_dinv(int n) {
    int i = blockIdx.x * blockDim.x + threadIdx.x;
    if (i < n) g_dinv[i] = rsqrtf(g_deg[i]);
}

// K5: single-block exclusive scan of counts -> offsets (+ cursor copy)
__global__ void k_scan(int n) {
    __shared__ int sm[1024];
    int t = threadIdx.x;
    int chunk = (n + 1023) / 1024;
    int s = t * chunk;
    int e = min(s + chunk, n);
    int sum = 0;
    for (int i = s; i < e; i++) sum += g_counts[i];
    sm[t] = sum;
    __syncthreads();
    for (int d = 1; d < 1024; d <<= 1) {
        int v = (t >= d) ? sm[t - d] : 0;
        __syncthreads();
        sm[t] += v;
        __syncthreads();
    }
    int run = sm[t] - sum;  // exclusive prefix
    for (int i = s; i < e; i++) {
        g_offsets[i] = run;
        g_cursor[i]  = run;
        run += g_counts[i];
    }
    if (t == 1023) g_offsets[n] = sm[1023];
}

// K6: scatter edges into CSR-by-dst, fusing norm computation.
__global__ void k_scatter(const int* __restrict__ src,
                          const int* __restrict__ dst,
                          const float* __restrict__ w, int E) {
    int e = blockIdx.x * blockDim.x + threadIdx.x;
    if (e < E) {
        int s = src[e];
        int d = dst[e];
        int pos = atomicAdd(&g_cursor[d], 1);
        g_csr_src[pos]  = s;
        g_csr_norm[pos] = g_dinv[s] * w[e] * g_dinv[d];
    }
}

// ---------------------------------------------------------------------------
// K7: xw = x @ W.  64x128 tile per block, W fully in smem,
// thread computes 4 rows x 8 columns (columns strided by 16 -> conflict-free LDS).
// ---------------------------------------------------------------------------
#define XS_STRIDE 132  // padded row (floats), 16B-multiple
__global__ void k_sgemm(const float* __restrict__ x, int n) {
    extern __shared__ float smem[];
    float* xs = smem;                    // [TM][XS_STRIDE]
    float* ws = smem + TM * XS_STRIDE;   // [128][128]
    int t = threadIdx.x;
    int row0 = blockIdx.x * TM;

    // stage W (16384 floats)
    const float4* W4  = (const float4*)g_W;
    float4*       ws4 = (float4*)ws;
    for (int i = t; i < FDIM * FDIM / 4; i += 256) ws4[i] = W4[i];

    // stage x tile (64 rows x 128 cols) with zero-pad for OOB rows
    for (int i = t; i < TM * 32; i += 256) {
        int r  = i / 32;
        int c4 = i % 32;
        int gr = row0 + r;
        float4 v = (gr < n) ? ((const float4*)x)[gr * 32 + c4]
                            : make_float4(0.f, 0.f, 0.f, 0.f);
        ((float4*)(xs + r * XS_STRIDE))[c4] = v;
    }
    __syncthreads();

    int tx = t % 16;        // column lane: cols tx + 16*h
    int ty = t / 16;        // row group:  rows ty*4 + r
    float acc[4][8];
#pragma unroll
    for (int r = 0; r < 4; r++)
#pragma unroll
        for (int h = 0; h < 8; h++) acc[r][h] = 0.f;

    const float* xsr = xs + (ty * 4) * XS_STRIDE;
#pragma unroll 4
    for (int k = 0; k < FDIM; k++) {
        float a0 = xsr[k];
        float a1 = xsr[XS_STRIDE + k];
        float a2 = xsr[2 * XS_STRIDE + k];
        float a3 = xsr[3 * XS_STRIDE + k];
        const float* wrow = ws + k * FDIM + tx;
        float b[8];
#pragma unroll
        for (int h = 0; h < 8; h++) b[h] = wrow[16 * h];
#pragma unroll
        for (int h = 0; h < 8; h++) {
            acc[0][h] += a0 * b[h];
            acc[1][h] += a1 * b[h];
            acc[2][h] += a2 * b[h];
            acc[3][h] += a3 * b[h];
        }
    }

#pragma unroll
    for (int r = 0; r < 4; r++) {
        int gr = row0 + ty * 4 + r;
        if (gr < n) {
            float* o = g_xw + gr * FDIM + tx;
#pragma unroll
            for (int h = 0; h < 8; h++) o[16 * h] = acc[r][h];
        }
    }
}

// ---------------------------------------------------------------------------
// K8: warp-per-node gather + tanh + final linear (fused; h never materialized)
// lane handles 4 contiguous features (float4).
// ---------------------------------------------------------------------------
__global__ void k_gather(const float* __restrict__ wlin,
                         const float* __restrict__ blin,
                         float* __restrict__ out, int n) {
    int gw   = (blockIdx.x * blockDim.x + threadIdx.x) >> 5;
    int lane = threadIdx.x & 31;
    if (gw >= n) return;

    const float4* xw4 = (const float4*)g_xw;
    float di = g_dinv[gw];
    float sn = di * di;                 // self-loop norm (w=1)
    float4 acc = xw4[gw * 32 + lane];
    acc.x *= sn; acc.y *= sn; acc.z *= sn; acc.w *= sn;

    int beg = g_offsets[gw];
    int end = g_offsets[gw + 1];
#pragma unroll 4
    for (int e = beg; e < end; e++) {
        int   s  = g_csr_src[e];
        float nm = g_csr_norm[e];
        float4 v = xw4[s * 32 + lane];
        acc.x += nm * v.x;
        acc.y += nm * v.y;
        acc.z += nm * v.z;
        acc.w += nm * v.w;
    }

    float4 wl = ((const float4*)wlin)[lane];
    float p = tanhf(acc.x) * wl.x + tanhf(acc.y) * wl.y +
              tanhf(acc.z) * wl.z + tanhf(acc.w) * wl.w;
#pragma unroll
    for (int o = 16; o; o >>= 1) p += __shfl_down_sync(0xffffffffu, p, o);
    if (lane == 0) out[gw] = p + blin[0];
}

// ---------------------------------------------------------------------------
extern "C" void kernel_launch(void* const* d_in, const int* in_sizes, int n_in,
                              void* d_out, int out_size) {
    const float* x    = (const float*)d_in[0];
    const int*   ei   = (const int*)  d_in[1];
    const float* ew   = (const float*)d_in[2];
    const float* W0   = (const float*)d_in[3];
    const float* Wih  = (const float*)d_in[4];
    const float* Whh  = (const float*)d_in[5];
    const float* bih  = (const float*)d_in[6];
    const float* bhh  = (const float*)d_in[7];
    const float* wlin = (const float*)d_in[8];
    const float* blin = (const float*)d_in[9];
    float* out = (float*)d_out;

    int N = in_sizes[0] / FDIM;
    int E = in_sizes[2];
    const int* src = ei;
    const int* dst = ei + E;

    k_evolve<<<FDIM, FDIM>>>(W0, Wih, Whh, bih, bhh);
    k_init<<<(N + 255) / 256, 256>>>(N);
    k_edge_count<<<(E + 255) / 256, 256>>>(dst, ew, E);
    k_dinv<<<(N + 255) / 256, 256>>>(N);
    k_scan<<<1, 1024>>>(N);
    k_scatter<<<(E + 255) / 256, 256>>>(src, dst, ew, E);

    int smem = (TM * XS_STRIDE + FDIM * FDIM) * (int)sizeof(float);  // 99328 B
    cudaFuncSetAttribute(k_sgemm, cudaFuncAttributeMaxDynamicSharedMemorySize, smem);
    k_sgemm<<<(N + TM - 1) / TM, 256, smem>>>(x, N);

    k_gather<<<(N * 32 + 255) / 256, 256>>>(wlin, blin, out, N);
}